// round 7
// baseline (speedup 1.0000x reference)
#include <cuda_runtime.h>
#include <cstdint>

#define NB 8
#define NQ 100000
#define NC 10
#define NPB (NQ*NC)          // 1,000,000 logits per batch
#define NP 20
#define TOPK 100
#define CAP 32768
#define KEEPMAX 2048
#define KEY0 0xC0400000u     // sortable key of +3.0f (speculative collect threshold)
#define BINS 4096
#define BIN_SHIFT 20

// ---- scratch (no allocations allowed) ----
__device__ int                g_cnt[NB];          // zero-initialized; final_k resets it
__device__ unsigned long long g_cand[NB][CAP];

__device__ __forceinline__ unsigned int f2key(float f) {
    unsigned int u = __float_as_uint(f);
    return (u & 0x80000000u) ? ~u : (u | 0x80000000u);
}
__device__ __forceinline__ float key2f(unsigned int k) {
    unsigned int u = (k & 0x80000000u) ? (k & 0x7FFFFFFFu) : ~k;
    return __uint_as_float(u);
}

__device__ __forceinline__ void push_cand(int b, unsigned int key, unsigned int lidx) {
    int pos = atomicAdd(&g_cnt[b], 1);
    if (pos < CAP)
        g_cand[b][pos] = ((unsigned long long)key << 32) | (unsigned int)(~lidx);
}

// ---- Pass 1: single streaming scan, speculative candidate collection only ----
__global__ void scan_k(const float* __restrict__ cls) {
    const float4* src = (const float4*)cls;
    const unsigned int n4 = (unsigned int)NB * (NPB / 4);
    const unsigned int stride = gridDim.x * blockDim.x;
    for (unsigned int i = blockIdx.x * blockDim.x + threadIdx.x; i < n4; i += stride) {
        float4 v = __ldcs(src + i);
        unsigned int k0 = f2key(v.x), k1 = f2key(v.y), k2 = f2key(v.z), k3 = f2key(v.w);
        if ((k0 >= KEY0) | (k1 >= KEY0) | (k2 >= KEY0) | (k3 >= KEY0)) {
            int b = (int)(i / (NPB / 4));
            unsigned int e = i * 4u - (unsigned int)b * (unsigned int)NPB;
            if (k0 >= KEY0) push_cand(b, k0, e + 0);
            if (k1 >= KEY0) push_cand(b, k1, e + 1);
            if (k2 >= KEY0) push_cand(b, k2, e + 2);
            if (k3 >= KEY0) push_cand(b, k3, e + 3);
        }
    }
}

// find largest bin such that count(keys >= bin<<SHIFT) >= TOPK, from shared hist.
// blockDim.x must be 512 (512 threads x 8 bins = 4096).
__device__ unsigned int find_cut(const unsigned int* hist,
                                 unsigned int* chunk, unsigned int* suff,
                                 unsigned int* out_cut) {
    const int tid = threadIdx.x;
    const int base = tid * 8;
    unsigned int h[8];
    unsigned int s = 0;
#pragma unroll
    for (int j = 0; j < 8; j++) { h[j] = hist[base + j]; s += h[j]; }
    chunk[tid] = s;
    __syncthreads();
    if (tid == 0) {
        unsigned int acc = 0;
        for (int t = 511; t >= 0; t--) { acc += chunk[t]; suff[t] = acc; }
    }
    __syncthreads();
    unsigned int above = (tid == 511) ? 0u : suff[tid + 1];
    if (above < TOPK && suff[tid] >= TOPK) {   // exactly one thread
        unsigned int acc = above;
        int cut = base;
        for (int j = 7; j >= 0; j--) {
            acc += h[j];
            if (acc >= TOPK) { cut = base + j; break; }
        }
        *out_cut = (unsigned int)cut << BIN_SHIFT;
    }
    __syncthreads();
    return *out_cut;
}

// ---- Pass 2: exact cutoff from candidates, top-100, masks, denorm, write ----
__global__ void __launch_bounds__(512) final_k(const float* __restrict__ cls,
                                               const float* __restrict__ bbox,
                                               const float* __restrict__ pts,
                                               float* __restrict__ out) {
    __shared__ unsigned int hist[BINS];
    __shared__ unsigned int chunk[512];
    __shared__ unsigned int suff[512];
    __shared__ unsigned int cut_s;
    __shared__ unsigned long long arr[KEEPMAX];
    __shared__ unsigned long long topc[TOPK];
    __shared__ int nkeep;
    __shared__ int mode_s;
    __shared__ float thr_s;

    const int b = blockIdx.x;
    const int tid = threadIdx.x;

    int cnt = g_cnt[b];
    if (cnt < TOPK || cnt > CAP) {
        // ---- fallback (never taken on this data): exact recollect ----
        if (tid == 0) g_cnt[b] = 0;
        for (int t = tid; t < BINS; t += blockDim.x) hist[t] = 0u;
        __syncthreads();
        const float* base = cls + (size_t)b * NPB;
        for (int i = tid; i < NPB; i += blockDim.x)
            atomicAdd(&hist[f2key(base[i]) >> BIN_SHIFT], 1u);
        __syncthreads();
        unsigned int ck = find_cut(hist, chunk, suff, &cut_s);
        for (int i = tid; i < NPB; i += blockDim.x) {
            unsigned int key = f2key(base[i]);
            if (key >= ck) push_cand(b, key, (unsigned int)i);
        }
        __syncthreads();
        cnt = g_cnt[b];
    }
    cnt = min(cnt, CAP);

    // ---- histogram over candidates only (~1.3k) ----
    for (int t = tid; t < BINS; t += blockDim.x) hist[t] = 0u;
    __syncthreads();
    for (int i = tid; i < cnt; i += blockDim.x)
        atomicAdd(&hist[(unsigned int)(g_cand[b][i] >> (32 + BIN_SHIFT))], 1u);
    __syncthreads();
    unsigned int ck = find_cut(hist, chunk, suff, &cut_s);

    // ---- filter candidates >= cutoff into shared ----
    if (tid == 0) nkeep = 0;
    __syncthreads();
    for (int i = tid; i < cnt; i += blockDim.x) {
        unsigned long long c = g_cand[b][i];
        if ((unsigned int)(c >> 32) >= ck) {
            int p = atomicAdd(&nkeep, 1);
            if (p < KEEPMAX) arr[p] = c;
        }
    }
    __syncthreads();
    const int n = min(nkeep, KEEPMAX);

    // ---- exact rank-by-count (composites distinct -> unique ranks) ----
    for (int r = tid; r < TOPK; r += blockDim.x) topc[r] = 0ULL;
    __syncthreads();
    for (int i = tid; i < n; i += blockDim.x) {
        unsigned long long c = arr[i];
        int rank = 0;
        for (int j = 0; j < n; j++) rank += (arr[j] > c);
        if (rank < TOPK) topc[rank] = c;
    }
    __syncthreads();

    if (tid == 0) {
        float maxs = 0.f;
        if (n > 0) {
            float f = key2f((unsigned int)(topc[0] >> 32));
            maxs = 1.f / (1.f + expf(-f));
        }
        int mode; float thr = 0.1f;
        if (maxs > 0.1f) mode = 0;
        else {
            float tmp = 0.1f; mode = 2;
            while (true) {
                tmp *= 0.9f;
                if (tmp < 0.01f) { mode = 2; break; }
                if (maxs >= tmp) { mode = 1; thr = tmp; break; }
            }
        }
        mode_s = mode; thr_s = thr;
    }
    __syncthreads();

    // output layout (float32, tuple order, C-contiguous each):
    float* oBox   = out;                       // [NB][TOPK][4]
    float* oScore = out + NB * TOPK * 4;       // [NB][TOPK]
    float* oLabel = oScore + NB * TOPK;        // [NB][TOPK]
    float* oPts   = oLabel + NB * TOPK;        // [NB][TOPK][NP][2]
    float* oMask  = oPts + NB * TOPK * NP * 2; // [NB][TOPK]

    for (int r = tid; r < TOPK; r += blockDim.x) {
        unsigned long long c = topc[r];
        const bool valid = (r < n);
        float score = 0.f, x1 = 0.f, y1 = 0.f, x2 = 0.f, y2 = 0.f;
        int label = 0, q = 0;
        bool mask = false;
        if (valid) {
            unsigned int key = (unsigned int)(c >> 32);
            unsigned int idx = ~(unsigned int)(c & 0xFFFFFFFFu);
            float f = key2f(key);
            score = 1.f / (1.f + expf(-f));
            label = (int)(idx % NC);
            q     = (int)(idx / NC);
            const float* bb = bbox + ((size_t)b * NQ + q) * 4;
            float cx = bb[0], cy = bb[1], w = bb[2], h = bb[3];
            x1 = (cx - w * 0.5f) * 30.f - 15.f;
            y1 = (cy - h * 0.5f) * 60.f - 30.f;
            x2 = (cx + w * 0.5f) * 30.f - 15.f;
            y2 = (cy + h * 0.5f) * 60.f - 30.f;
            bool rmask = x1 >= -20.f && y1 >= -35.f && x2 >= -20.f && y2 >= -35.f
                      && x1 <=  20.f && y1 <=  35.f && x2 <=  20.f && y2 <=  35.f;
            bool tm = (mode_s == 0) ? (score > 0.1f)
                    : (mode_s == 1) ? (score >= thr_s) : true;
            mask = rmask && tm;
        }
        const size_t ob = (size_t)b * TOPK + r;
        oBox[ob * 4 + 0] = mask ? x1 : 0.f;
        oBox[ob * 4 + 1] = mask ? y1 : 0.f;
        oBox[ob * 4 + 2] = mask ? x2 : 0.f;
        oBox[ob * 4 + 3] = mask ? y2 : 0.f;
        oScore[ob] = mask ? score : 0.f;
        oLabel[ob] = mask ? (float)label : 0.f;
        oMask[ob]  = mask ? 1.f : 0.f;
        const float* pp = pts + ((size_t)b * NQ + q) * (NP * 2);
#pragma unroll
        for (int j = 0; j < NP; j++) {
            float vx = 0.f, vy = 0.f;
            if (valid) { vx = pp[2 * j]; vy = pp[2 * j + 1]; }
            vx = vx * 30.f - 15.f;
            vy = vy * 60.f - 30.f;
            oPts[ob * (NP * 2) + 2 * j]     = mask ? vx : 0.f;
            oPts[ob * (NP * 2) + 2 * j + 1] = mask ? vy : 0.f;
        }
    }

    // ---- reset counter for next graph replay (after all reads) ----
    __syncthreads();
    if (tid == 0) g_cnt[b] = 0;
}

extern "C" void kernel_launch(void* const* d_in, const int* in_sizes, int n_in,
                              void* d_out, int out_size) {
    const float* cls  = (const float*)d_in[0];   // [8,100000,10]
    const float* bbox = (const float*)d_in[1];   // [8,100000,4]
    const float* pts  = (const float*)d_in[2];   // [8,100000,20,2]
    float* out = (float*)d_out;

    scan_k<<<1184, 256>>>(cls);                  // 8 blocks/SM x 148 SMs
    final_k<<<NB, 512>>>(cls, bbox, pts, out);
}

// round 8
// speedup vs baseline: 1.3236x; 1.3236x over previous
#include <cuda_runtime.h>
#include <cstdint>

#define NB 8
#define NQ 100000
#define NC 10
#define NPB (NQ*NC)          // 1,000,000 logits per batch
#define NP 20
#define TOPK 100
#define CAP 32768
#define KEEPMAX 2048
#define KEY0 0xC0400000u     // sortable key of +3.0f (speculative collect threshold)

// ---- scratch (no allocations allowed) ----
__device__ int                g_cnt[NB];          // zero-initialized; final_k resets it
__device__ unsigned long long g_cand[NB][CAP];

__device__ __forceinline__ unsigned int f2key(float f) {
    unsigned int u = __float_as_uint(f);
    return (u & 0x80000000u) ? ~u : (u | 0x80000000u);
}
__device__ __forceinline__ float key2f(unsigned int k) {
    unsigned int u = (k & 0x80000000u) ? (k & 0x7FFFFFFFu) : ~k;
    return __uint_as_float(u);
}
__device__ __forceinline__ void push_cand(int b, unsigned int key, unsigned int lidx) {
    int pos = atomicAdd(&g_cnt[b], 1);
    if (pos < CAP)
        g_cand[b][pos] = ((unsigned long long)key << 32) | (unsigned int)(~lidx);
}

// ---- Pass 1: streaming scan, 8 loads in flight per thread ----
#define SCAN_BLOCKS 977
#define SCAN_THREADS (SCAN_BLOCKS * 256)   // 250112 >= 2,000,000/8

__device__ __forceinline__ void proc4(float4 v, unsigned int i /*float4 idx*/) {
    unsigned int k0 = f2key(v.x), k1 = f2key(v.y), k2 = f2key(v.z), k3 = f2key(v.w);
    if ((k0 >= KEY0) | (k1 >= KEY0) | (k2 >= KEY0) | (k3 >= KEY0)) {
        int b = (int)(i / (NPB / 4));
        unsigned int e = i * 4u - (unsigned int)b * (unsigned int)NPB;
        if (k0 >= KEY0) push_cand(b, k0, e + 0);
        if (k1 >= KEY0) push_cand(b, k1, e + 1);
        if (k2 >= KEY0) push_cand(b, k2, e + 2);
        if (k3 >= KEY0) push_cand(b, k3, e + 3);
    }
}

__global__ void scan_k(const float* __restrict__ cls) {
    const float4* src = (const float4*)cls;
    const unsigned int n4 = (unsigned int)NB * (NPB / 4);   // 2,000,000
    const unsigned int S = SCAN_THREADS;
    const unsigned int t = blockIdx.x * blockDim.x + threadIdx.x;
    float4 v[8];
    bool ok[8];
#pragma unroll
    for (int j = 0; j < 8; j++) {
        unsigned int i = t + (unsigned int)j * S;
        ok[j] = (i < n4);
        if (ok[j]) v[j] = __ldcs(src + i);
    }
#pragma unroll
    for (int j = 0; j < 8; j++)
        if (ok[j]) proc4(v[j], t + (unsigned int)j * S);
}

// reversed (suffix) inclusive scan over 512 shared entries; blockDim.x == 512
__device__ __forceinline__ void suffix_scan(unsigned int* suff) {
    const int tid = threadIdx.x;
#pragma unroll
    for (int off = 1; off < 512; off <<= 1) {
        unsigned int u = suff[tid];
        if (tid + off < 512) u += suff[tid + off];
        __syncthreads();
        suff[tid] = u;
        __syncthreads();
    }
}

// ---- Pass 2: exact top-100 from candidates (two-level cut), masks, denorm ----
__global__ void __launch_bounds__(512) final_k(const float* __restrict__ cls,
                                               const float* __restrict__ bbox,
                                               const float* __restrict__ pts,
                                               float* __restrict__ out) {
    __shared__ unsigned int suff[512];
    __shared__ unsigned int cut_s;
    __shared__ unsigned long long arr[KEEPMAX];   // 16KB; aliased as fallback hist
    __shared__ unsigned long long topc[TOPK];
    __shared__ int nkeep;
    __shared__ int mode_s;
    __shared__ float thr_s;

    const int b = blockIdx.x;
    const int tid = threadIdx.x;

    int cnt = g_cnt[b];
    if (cnt < TOPK || cnt > CAP) {
        // ---- cold fallback: exact recollect via coarse 4096-bin histogram ----
        unsigned int* h4 = (unsigned int*)arr;    // 4096 * 4B = 16KB
        if (tid == 0) g_cnt[b] = 0;
        for (int t = tid; t < 4096; t += 512) h4[t] = 0u;
        __syncthreads();
        const float* basep = cls + (size_t)b * NPB;
        for (int i = tid; i < NPB; i += 512)
            atomicAdd(&h4[f2key(basep[i]) >> 20], 1u);
        __syncthreads();
        if (tid == 0) {
            unsigned int acc = 0; int cut = 0;
            for (int t = 4095; t >= 0; t--) { acc += h4[t]; if (acc >= TOPK) { cut = t; break; } }
            cut_s = (unsigned int)cut << 20;
        }
        __syncthreads();
        unsigned int ck = cut_s;
        for (int i = tid; i < NPB; i += 512) {
            unsigned int key = f2key(basep[i]);
            if (key >= ck) push_cand(b, key, (unsigned int)i);
        }
        __syncthreads();
        cnt = g_cnt[b];
    }
    cnt = min(cnt, CAP);
    const unsigned long long* cand = g_cand[b];

    // ---- level 1: 512-bin coarse cut on key>>23 (sign+exponent) ----
    suff[tid] = 0u;
    __syncthreads();
    for (int i = tid; i < cnt; i += 512)
        atomicAdd(&suff[(unsigned int)(cand[i] >> (32 + 23))], 1u);
    __syncthreads();
    suffix_scan(suff);
    if (suff[tid] >= TOPK && (tid == 511 || suff[tid + 1] < TOPK))
        cut_s = (unsigned int)tid;
    __syncthreads();
    const unsigned int base = cut_s << 23;
    __syncthreads();

    // ---- level 2: 512 bins of width 2^14 within/above the coarse bin ----
    suff[tid] = 0u;
    __syncthreads();
    for (int i = tid; i < cnt; i += 512) {
        unsigned int key = (unsigned int)(cand[i] >> 32);
        if (key >= base) atomicAdd(&suff[min(511u, (key - base) >> 14)], 1u);
    }
    __syncthreads();
    suffix_scan(suff);
    if (suff[tid] >= TOPK && (tid == 511 || suff[tid + 1] < TOPK))
        cut_s = (unsigned int)tid;
    __syncthreads();
    const unsigned int ck = base + (cut_s << 14);

    // ---- filter candidates >= ck (n ~= 100-110) ----
    if (tid == 0) nkeep = 0;
    __syncthreads();
    for (int i = tid; i < cnt; i += 512) {
        unsigned long long c = cand[i];
        if ((unsigned int)(c >> 32) >= ck) {
            int p = atomicAdd(&nkeep, 1);
            if (p < KEEPMAX) arr[p] = c;
        }
    }
    __syncthreads();
    const int n = min(nkeep, KEEPMAX);

    // ---- exact rank-by-count (composites distinct -> unique ranks) ----
    if (tid < TOPK) topc[tid] = 0ULL;
    __syncthreads();
    for (int i = tid; i < n; i += 512) {
        unsigned long long c = arr[i];
        int rank = 0;
        for (int j = 0; j < n; j++) rank += (arr[j] > c);
        if (rank < TOPK) topc[rank] = c;
    }
    __syncthreads();

    if (tid == 0) {
        float maxs = 0.f;
        if (n > 0) {
            float f = key2f((unsigned int)(topc[0] >> 32));
            maxs = 1.f / (1.f + expf(-f));
        }
        int mode; float thr = 0.1f;
        if (maxs > 0.1f) mode = 0;
        else {
            float tmp = 0.1f; mode = 2;
            while (true) {
                tmp *= 0.9f;
                if (tmp < 0.01f) { mode = 2; break; }
                if (maxs >= tmp) { mode = 1; thr = tmp; break; }
            }
        }
        mode_s = mode; thr_s = thr;
    }
    __syncthreads();

    // output layout (float32, tuple order, C-contiguous each):
    float* oBox   = out;                       // [NB][TOPK][4]
    float* oScore = out + NB * TOPK * 4;       // [NB][TOPK]
    float* oLabel = oScore + NB * TOPK;        // [NB][TOPK]
    float* oPts   = oLabel + NB * TOPK;        // [NB][TOPK][NP][2]
    float* oMask  = oPts + NB * TOPK * NP * 2; // [NB][TOPK]

    for (int r = tid; r < TOPK; r += 512) {
        unsigned long long c = topc[r];
        const bool valid = (r < n);
        float score = 0.f, x1 = 0.f, y1 = 0.f, x2 = 0.f, y2 = 0.f;
        int label = 0, q = 0;
        bool mask = false;
        if (valid) {
            unsigned int key = (unsigned int)(c >> 32);
            unsigned int idx = ~(unsigned int)(c & 0xFFFFFFFFu);
            float f = key2f(key);
            score = 1.f / (1.f + expf(-f));
            label = (int)(idx % NC);
            q     = (int)(idx / NC);
            const float* bb = bbox + ((size_t)b * NQ + q) * 4;
            float cx = bb[0], cy = bb[1], w = bb[2], h = bb[3];
            x1 = (cx - w * 0.5f) * 30.f - 15.f;
            y1 = (cy - h * 0.5f) * 60.f - 30.f;
            x2 = (cx + w * 0.5f) * 30.f - 15.f;
            y2 = (cy + h * 0.5f) * 60.f - 30.f;
            bool rmask = x1 >= -20.f && y1 >= -35.f && x2 >= -20.f && y2 >= -35.f
                      && x1 <=  20.f && y1 <=  35.f && x2 <=  20.f && y2 <=  35.f;
            bool tm = (mode_s == 0) ? (score > 0.1f)
                    : (mode_s == 1) ? (score >= thr_s) : true;
            mask = rmask && tm;
        }
        const size_t ob = (size_t)b * TOPK + r;
        oBox[ob * 4 + 0] = mask ? x1 : 0.f;
        oBox[ob * 4 + 1] = mask ? y1 : 0.f;
        oBox[ob * 4 + 2] = mask ? x2 : 0.f;
        oBox[ob * 4 + 3] = mask ? y2 : 0.f;
        oScore[ob] = mask ? score : 0.f;
        oLabel[ob] = mask ? (float)label : 0.f;
        oMask[ob]  = mask ? 1.f : 0.f;
        const float* pp = pts + ((size_t)b * NQ + q) * (NP * 2);
#pragma unroll
        for (int j = 0; j < NP; j++) {
            float vx = 0.f, vy = 0.f;
            if (valid) { vx = pp[2 * j]; vy = pp[2 * j + 1]; }
            vx = vx * 30.f - 15.f;
            vy = vy * 60.f - 30.f;
            oPts[ob * (NP * 2) + 2 * j]     = mask ? vx : 0.f;
            oPts[ob * (NP * 2) + 2 * j + 1] = mask ? vy : 0.f;
        }
    }

    // ---- reset counter for next graph replay (after all reads) ----
    __syncthreads();
    if (tid == 0) g_cnt[b] = 0;
}

extern "C" void kernel_launch(void* const* d_in, const int* in_sizes, int n_in,
                              void* d_out, int out_size) {
    const float* cls  = (const float*)d_in[0];   // [8,100000,10]
    const float* bbox = (const float*)d_in[1];   // [8,100000,4]
    const float* pts  = (const float*)d_in[2];   // [8,100000,20,2]
    float* out = (float*)d_out;

    scan_k<<<SCAN_BLOCKS, 256>>>(cls);
    final_k<<<NB, 512>>>(cls, bbox, pts, out);
}

// round 10
// speedup vs baseline: 1.5768x; 1.1913x over previous
#include <cuda_runtime.h>
#include <cstdint>

#define NB 8
#define NQ 100000
#define NC 10
#define NPB (NQ*NC)          // 1,000,000 logits per batch
#define N4B (NPB/4)          // 250,000 float4 per batch
#define NP 20
#define TOPK 100
#define CAP 32768
#define KEY0 0xC0400000u     // sortable key of +3.0f (speculative threshold)
#define BLK 512
#define F4_PER_BLK 4096      // BLK * 8
#define BLK_PER_B 62         // 62*4096 = 253952 >= 250000
#define SHC 2048             // shared candidate cache
#define ARRC 1024            // filtered set cap (fast rank path)

// ---- scratch (zero-initialized; reset by finisher for graph replay) ----
__device__ int                g_cnt[NB];
__device__ int                g_done[NB];
__device__ unsigned long long g_cand[NB][CAP];

__device__ __forceinline__ unsigned int f2key(float f) {
    unsigned int u = __float_as_uint(f);
    return (u & 0x80000000u) ? ~u : (u | 0x80000000u);
}
__device__ __forceinline__ float key2f(unsigned int k) {
    unsigned int u = (k & 0x80000000u) ? (k & 0x7FFFFFFFu) : ~k;
    return __uint_as_float(u);
}
__device__ __forceinline__ void push_cand(int b, unsigned int key, unsigned int lidx) {
    int pos = atomicAdd(&g_cnt[b], 1);
    if (pos < CAP)
        g_cand[b][pos] = ((unsigned long long)key << 32) | (unsigned int)(~lidx);
}
__device__ __forceinline__ void proc4(float4 v, int b, unsigned int e) {
    unsigned int k0 = f2key(v.x), k1 = f2key(v.y), k2 = f2key(v.z), k3 = f2key(v.w);
    if ((k0 >= KEY0) | (k1 >= KEY0) | (k2 >= KEY0) | (k3 >= KEY0)) {
        if (k0 >= KEY0) push_cand(b, k0, e + 0);
        if (k1 >= KEY0) push_cand(b, k1, e + 1);
        if (k2 >= KEY0) push_cand(b, k2, e + 2);
        if (k3 >= KEY0) push_cand(b, k3, e + 3);
    }
}

// suffix-inclusive count at bin tid, via warp shuffles. blockDim.x == 512.
// returns Sum_{t >= tid} cntv_t ; wsum is 16-entry shared scratch.
__device__ __forceinline__ unsigned int suffix_of(unsigned int cntv, unsigned int* wsum) {
    const int tid = threadIdx.x, lane = tid & 31, wid = tid >> 5;
    unsigned int v = cntv;
#pragma unroll
    for (int off = 1; off < 32; off <<= 1) {
        unsigned int u = __shfl_down_sync(0xFFFFFFFFu, v, off);
        if (lane + off < 32) v += u;
    }
    if (lane == 0) wsum[wid] = v;   // warp total
    __syncthreads();
    if (tid < 16) {
        unsigned int w = wsum[tid];
#pragma unroll
        for (int off = 1; off < 16; off <<= 1) {
            unsigned int u = __shfl_down_sync(0xFFFFu, w, off);
            if (tid + off < 16) w += u;
        }
        wsum[tid] = w;              // inclusive suffix over warp totals
    }
    __syncthreads();
    return v + ((wid < 15) ? wsum[wid + 1] : 0u);
}

__global__ void __launch_bounds__(BLK) fused_k(const float* __restrict__ cls,
                                               const float* __restrict__ bbox,
                                               const float* __restrict__ pts,
                                               float* __restrict__ out) {
    const int b = blockIdx.y;
    const int tid = threadIdx.x;

    // ================= scan phase =================
    {
        const float4* src = (const float4*)(cls + (size_t)b * NPB);
        const unsigned int base = blockIdx.x * F4_PER_BLK + tid;
#pragma unroll
        for (int g = 0; g < 2; g++) {
            float4 v[4]; bool ok[4];
#pragma unroll
            for (int j = 0; j < 4; j++) {
                unsigned int i = base + (unsigned int)(g * 4 + j) * BLK;
                ok[j] = (i < N4B);
                if (ok[j]) v[j] = __ldcs(src + i);
            }
#pragma unroll
            for (int j = 0; j < 4; j++)
                if (ok[j]) proc4(v[j], b, (base + (unsigned int)(g * 4 + j) * BLK) * 4u);
        }
    }
    // make THIS thread's g_cand stores visible device-wide before arrival
    __threadfence();
    __syncthreads();

    // ---- last block of this batch becomes the finisher ----
    __shared__ int isLast;
    if (tid == 0)
        isLast = (atomicAdd(&g_done[b], 1) == BLK_PER_B - 1);
    __syncthreads();
    if (!isLast) return;
    __threadfence();

    // ================= finisher phase =================
    __shared__ unsigned long long shcand[SHC];     // 16KB (aliased as fallback hist)
    __shared__ unsigned long long arr[ARRC];       // 8KB filtered set
    __shared__ unsigned long long topc[TOPK];
    __shared__ unsigned int hcnt[512];
    __shared__ unsigned int wsum[16];
    __shared__ unsigned int cut_s;
    __shared__ int nkeep, mode_s;
    __shared__ float thr_s;
    __shared__ int   qA[TOPK];
    __shared__ unsigned char mA[TOPK];

    int cnt = g_cnt[b];
    if (cnt < TOPK || cnt > CAP) {
        // ---- cold fallback (never taken on this data): exact recollect ----
        unsigned int* h4 = (unsigned int*)shcand;          // 4096 bins
        if (tid == 0) g_cnt[b] = 0;
        for (int t = tid; t < 4096; t += BLK) h4[t] = 0u;
        __syncthreads();
        const float* basep = cls + (size_t)b * NPB;
        for (int i = tid; i < NPB; i += BLK)
            atomicAdd(&h4[f2key(basep[i]) >> 20], 1u);
        __syncthreads();
        if (tid == 0) {
            unsigned int acc = 0; int cut = 0;
            for (int t = 4095; t >= 0; t--) { acc += h4[t]; if (acc >= TOPK) { cut = t; break; } }
            cut_s = (unsigned int)cut << 20;
        }
        __syncthreads();
        unsigned int ckf = cut_s;
        for (int i = tid; i < NPB; i += BLK) {
            unsigned int key = f2key(basep[i]);
            if (key >= ckf) push_cand(b, key, (unsigned int)i);
        }
        __syncthreads();
        cnt = min(g_cnt[b], CAP);
        __syncthreads();
    }

    // cache candidates in shared (single global read)
    const unsigned long long* gc = g_cand[b];
    const bool cached = (cnt <= SHC);
    if (cached) {
        for (int i = tid; i < cnt; i += BLK) shcand[i] = gc[i];
        __syncthreads();
    }
    const unsigned long long* cand = cached ? (const unsigned long long*)shcand : gc;

    // ---- level 1: 512-bin cut on key>>23 ----
    hcnt[tid] = 0u;
    __syncthreads();
    for (int i = tid; i < cnt; i += BLK)
        atomicAdd(&hcnt[(unsigned int)(cand[i] >> (32 + 23))], 1u);
    __syncthreads();
    {
        unsigned int cv = hcnt[tid];
        unsigned int s = suffix_of(cv, wsum);
        if (s >= TOPK && s - cv < TOPK) cut_s = (unsigned int)tid;
    }
    __syncthreads();
    const unsigned int basek = cut_s << 23;
    __syncthreads();

    // ---- level 2: 512 bins of width 2^14 ----
    hcnt[tid] = 0u;
    __syncthreads();
    for (int i = tid; i < cnt; i += BLK) {
        unsigned int key = (unsigned int)(cand[i] >> 32);
        if (key >= basek) atomicAdd(&hcnt[min(511u, (key - basek) >> 14)], 1u);
    }
    __syncthreads();
    {
        unsigned int cv = hcnt[tid];
        unsigned int s = suffix_of(cv, wsum);
        if (s >= TOPK && s - cv < TOPK) cut_s = (unsigned int)tid;
    }
    __syncthreads();
    const unsigned int ck = basek + (cut_s << 14);

    // ---- filter >= ck into shared arr ----
    if (tid == 0) nkeep = 0;
    __syncthreads();
    for (int i = tid; i < cnt; i += BLK) {
        unsigned long long c = cand[i];
        if ((unsigned int)(c >> 32) >= ck) {
            int p = atomicAdd(&nkeep, 1);
            if (p < ARRC) arr[p] = c;
        }
    }
    __syncthreads();
    const int n = nkeep;

    // ---- exact rank-by-count (composites distinct -> unique ranks) ----
    if (tid < TOPK) topc[tid] = 0ULL;
    __syncthreads();
    if (n <= ARRC) {
        for (int i = tid; i < n; i += BLK) {
            unsigned long long c = arr[i];
            int rank = 0;
            for (int j = 0; j < n; j++) rank += (arr[j] > c);
            if (rank < TOPK) topc[rank] = c;
        }
    } else {
        // degenerate ties overflow (never on this data): rank over full list
        for (int i = tid; i < cnt; i += BLK) {
            unsigned long long c = cand[i];
            if ((unsigned int)(c >> 32) >= ck) {
                int rank = 0;
                for (int j = 0; j < cnt; j++) rank += (cand[j] > c);
                if (rank < TOPK) topc[rank] = c;
            }
        }
    }
    __syncthreads();

    if (tid == 0) {
        float f = key2f((unsigned int)(topc[0] >> 32));
        float maxs = 1.f / (1.f + expf(-f));
        int mode; float thr = 0.1f;
        if (maxs > 0.1f) mode = 0;
        else {
            float tmp = 0.1f; mode = 2;
            while (true) {
                tmp *= 0.9f;
                if (tmp < 0.01f) { mode = 2; break; }
                if (maxs >= tmp) { mode = 1; thr = tmp; break; }
            }
        }
        mode_s = mode; thr_s = thr;
    }
    __syncthreads();

    // output layout (float32, tuple order, C-contiguous each):
    float* oBox   = out;                       // [NB][TOPK][4]
    float* oScore = out + NB * TOPK * 4;       // [NB][TOPK]
    float* oLabel = oScore + NB * TOPK;        // [NB][TOPK]
    float* oPts   = oLabel + NB * TOPK;        // [NB][TOPK][NP][2]
    float* oMask  = oPts + NB * TOPK * NP * 2; // [NB][TOPK]

    // ---- stage 1: per-rank metadata + box/score/label/mask writes ----
    if (tid < TOPK) {
        const int r = tid;
        unsigned long long c = topc[r];
        const bool valid = (r < n);
        float score = 0.f, x1 = 0.f, y1 = 0.f, x2 = 0.f, y2 = 0.f;
        int label = 0, q = 0;
        bool mask = false;
        if (valid) {
            unsigned int key = (unsigned int)(c >> 32);
            unsigned int idx = ~(unsigned int)(c & 0xFFFFFFFFu);
            float f = key2f(key);
            score = 1.f / (1.f + expf(-f));
            label = (int)(idx % NC);
            q     = (int)(idx / NC);
            const float4 bb = __ldg((const float4*)(bbox + ((size_t)b * NQ + q) * 4));
            float cx = bb.x, cy = bb.y, w = bb.z, h = bb.w;
            x1 = (cx - w * 0.5f) * 30.f - 15.f;
            y1 = (cy - h * 0.5f) * 60.f - 30.f;
            x2 = (cx + w * 0.5f) * 30.f - 15.f;
            y2 = (cy + h * 0.5f) * 60.f - 30.f;
            bool rmask = x1 >= -20.f && y1 >= -35.f && x2 >= -20.f && y2 >= -35.f
                      && x1 <=  20.f && y1 <=  35.f && x2 <=  20.f && y2 <=  35.f;
            bool tm = (mode_s == 0) ? (score > 0.1f)
                    : (mode_s == 1) ? (score >= thr_s) : true;
            mask = rmask && tm;
        }
        qA[r] = q;
        mA[r] = mask ? 1 : 0;
        const size_t ob = (size_t)b * TOPK + r;
        ((float4*)oBox)[ob] = mask ? make_float4(x1, y1, x2, y2)
                                   : make_float4(0.f, 0.f, 0.f, 0.f);
        oScore[ob] = mask ? score : 0.f;
        oLabel[ob] = mask ? (float)label : 0.f;
        oMask[ob]  = mask ? 1.f : 0.f;
    }
    __syncthreads();

    // ---- stage 2: pts gather, vectorized and spread over all threads ----
    // 100 rows x 10 float4 chunks (40 floats per row)
    for (int t = tid; t < TOPK * 10; t += BLK) {
        const int r = t / 10, c4 = t % 10;
        const bool mk = mA[r] != 0;
        float4 o = make_float4(0.f, 0.f, 0.f, 0.f);
        if (mk) {
            const float4 v = __ldg((const float4*)(pts + ((size_t)b * NQ + qA[r]) * (NP * 2)) + c4);
            o.x = v.x * 30.f - 15.f;
            o.y = v.y * 60.f - 30.f;
            o.z = v.z * 30.f - 15.f;
            o.w = v.w * 60.f - 30.f;
        }
        ((float4*)oPts)[(size_t)b * TOPK * 10 + t] = o;
    }

    // ---- reset scratch for next graph replay ----
    __syncthreads();
    if (tid == 0) { g_cnt[b] = 0; g_done[b] = 0; }
}

extern "C" void kernel_launch(void* const* d_in, const int* in_sizes, int n_in,
                              void* d_out, int out_size) {
    const float* cls  = (const float*)d_in[0];   // [8,100000,10]
    const float* bbox = (const float*)d_in[1];   // [8,100000,4]
    const float* pts  = (const float*)d_in[2];   // [8,100000,20,2]
    float* out = (float*)d_out;

    dim3 grid(BLK_PER_B, NB);
    fused_k<<<grid, BLK>>>(cls, bbox, pts, out);
}